// round 11
// baseline (speedup 1.0000x reference)
#include <cuda_runtime.h>
#include <cuda_bf16.h>
#include <cstdint>

// Problem dims (fixed by the dataset)
#define BB 4
#define CC 32
#define HH 64
#define WW 64
#define KK 64
#define HW 4096          // H*W
#define CAPK 1152        // max nnz per RF

// ---------- static device scratch (no allocations allowed) ----------
__device__ float2 g_kpack[KK * CAPK];   // k-major: {rf value, pixel idx bits}
__device__ int    g_knnz [KK];
__device__ float2 g_ppack[KK * HW];     // px-major: {rf value, k bits}, [j][px]
__device__ int    g_pcnt [HW];

// ============================================================================
// Prep kernel: 96 blocks x 256 threads. (unchanged from R10)
// ============================================================================
__global__ void __launch_bounds__(256, 4)
rf_prep_kernel(const float* __restrict__ rfs)
{
    int tid  = threadIdx.x;
    int warp = tid >> 5;
    int lane = tid & 31;

    if (blockIdx.x < KK) {
        // ---- k-major compaction for k = blockIdx.x ----
        int k = blockIdx.x;
        const float* r = rfs + k * HW;
        __shared__ float2 stage[CAPK];      // 9216 B
        __shared__ int    wbase[9];

        int px0 = tid * 16;
        float v[16];
        #pragma unroll
        for (int q = 0; q < 4; q++) {
            float4 f = ((const float4*)(r + px0))[q];
            v[q * 4 + 0] = f.x; v[q * 4 + 1] = f.y;
            v[q * 4 + 2] = f.z; v[q * 4 + 3] = f.w;
        }
        int cnt = 0;
        #pragma unroll
        for (int j = 0; j < 16; j++) cnt += (v[j] > 0.0f);

        int incl = cnt;
        #pragma unroll
        for (int o = 1; o < 32; o <<= 1) {
            int t = __shfl_up_sync(0xffffffffu, incl, o);
            if (lane >= o) incl += t;
        }
        if (lane == 31) wbase[warp] = incl;
        __syncthreads();
        if (warp == 0 && lane < 8) {
            int t = wbase[lane];
            int e = t;
            #pragma unroll
            for (int o = 1; o < 8; o <<= 1) {
                int x = __shfl_up_sync(0xffu, e, o);
                if (lane >= o) e += x;
            }
            wbase[lane] = e - t;
            if (lane == 7) wbase[8] = e;
        }
        __syncthreads();

        int off = wbase[warp] + (incl - cnt);
        #pragma unroll
        for (int j = 0; j < 16; j++) {
            if (v[j] > 0.0f) {
                if (off < CAPK) {
                    float2 e; e.x = v[j]; e.y = __int_as_float(px0 + j);
                    stage[off] = e;
                }
                off++;
            }
        }
        __syncthreads();

        int total = wbase[8];
        if (total > CAPK) total = CAPK;
        float2* kp = g_kpack + k * CAPK;
        for (int i = tid; i < total; i += 256)
            kp[i] = stage[i];
        if (tid == 0) g_knnz[k] = total;
    } else {
        // ---- pixel-major compaction: 128 px per block, smem tile 64x128 ----
        int pxbase = (blockIdx.x - KK) * 128;     // 32 blocks x 128 = 4096
        __shared__ float tile[KK * 128];          // 32 KB

        #pragma unroll
        for (int it = 0; it < 32; it++) {
            int idx = it * 256 + tid;
            int row = idx >> 7;
            int col = idx & 127;
            tile[idx] = rfs[row * HW + pxbase + col];
        }
        __syncthreads();

        if (tid < 128) {
            int px = pxbase + tid;
            int cnt = 0;
            #pragma unroll 16
            for (int k = 0; k < KK; k++) {
                float g = tile[k * 128 + tid];
                if (g > 0.0f) {
                    float2 e; e.x = g; e.y = __int_as_float(k);
                    g_ppack[cnt * HW + px] = e;
                    cnt++;
                }
            }
            g_pcnt[px] = cnt;
        }
    }
}

// ============================================================================
// Fused main kernel: grid = 256, cluster = 2 CTAs per image, block = 1024.
//   CTA rank r of image bc: Phase A computes denoms for k = r*32 .. r*32+32
//   (one warp per k), exchanges the peer's 32 denoms via DSMEM after a
//   cluster barrier, then Phase B accumulates h for pixel half r and pools.
// ============================================================================
__global__ void __launch_bounds__(1024, 2) __cluster_dims__(2, 1, 1)
rf_main_kernel(const float* __restrict__ u, float* __restrict__ out)
{
    __shared__ float u_s[HW];         // 16 KB (full image)
    __shared__ float h_s[HW / 2];     // 8 KB (own half)
    __shared__ float invd_s[KK + 1];

    int tid  = threadIdx.x;
    int warp = tid >> 5;              // 0..31
    int lane = tid & 31;
    int bc   = blockIdx.x >> 1;
    uint32_t rank;
    asm("mov.u32 %0, %%cluster_ctarank;" : "=r"(rank));

    ((float4*)u_s)[tid] = ((const float4*)(u + (size_t)bc * HW))[tid];
    if (tid == 0) invd_s[KK] = 0.0f;
    __syncthreads();

    // ---- Phase A: this CTA's 32 denominators ----
    {
        int k = (rank << 5) + warp;
        int n = g_knnz[k];
        const float2* kp = g_kpack + k * CAPK;
        float s = 0.0f;
        #pragma unroll 4
        for (int i = lane; i < n; i += 32) {
            float2 e = kp[i];
            s += __expf(u_s[__float_as_int(e.y)] * e.x);
        }
        #pragma unroll
        for (int o = 16; o; o >>= 1) s += __shfl_xor_sync(0xffffffffu, s, o);
        if (lane == 0) invd_s[k] = 1.0f / (1.0f + s);
    }

    // ---- exchange: cluster barrier, then pull peer's 32 denoms via DSMEM ----
    asm volatile("barrier.cluster.arrive.aligned;" ::: "memory");
    asm volatile("barrier.cluster.wait.aligned;"   ::: "memory");
    if (tid < 32) {
        int idx = ((rank ^ 1u) << 5) + tid;       // peer's k range
        uint32_t laddr;
        asm("{ .reg .u64 t; cvta.to.shared.u64 t, %1; cvt.u32.u64 %0, t; }"
            : "=r"(laddr) : "l"(&invd_s[idx]));
        uint32_t raddr;
        asm("mapa.shared::cluster.u32 %0, %1, %2;" : "=r"(raddr)
            : "r"(laddr), "r"(rank ^ 1u));
        float v;
        asm volatile("ld.shared::cluster.f32 %0, [%1];" : "=f"(v) : "r"(raddr));
        invd_s[idx] = v;
    }
    __syncthreads();

    // ---- Phase B: per-pixel h on own half; 2 pixels per thread ----
    int pbase = rank * (HW / 2);
    {
        float uv0 = u_s[pbase + tid], uv1 = u_s[pbase + tid + 1024];
        int px0 = pbase + tid, px1 = pbase + tid + 1024;
        int c0 = g_pcnt[px0], c1 = g_pcnt[px1];
        int cmax = (c0 > c1) ? c0 : c1;
        float h0 = 0.0f, h1 = 0.0f;
        for (int j = 0; j < cmax; j++) {
            if (j < c0) {
                float2 e = g_ppack[j * HW + px0];
                h0 += __expf(uv0 * e.x) * invd_s[__float_as_int(e.y)];
            }
            if (j < c1) {
                float2 e = g_ppack[j * HW + px1];
                h1 += __expf(uv1 * e.x) * invd_s[__float_as_int(e.y)];
            }
        }
        h_s[tid] = h0;
        h_s[tid + 1024] = h1;
    }
    __syncthreads();

    // ---- Phase C: 2x2 block max: 512 outputs for this half ----
    if (tid < 512) {
        int oy = tid >> 5, ox = tid & 31;         // oy 0..15 within half
        int p0 = (oy * 2) * WW + ox * 2;
        float m = fmaxf(fmaxf(h_s[p0], h_s[p0 + 1]),
                        fmaxf(h_s[p0 + WW], h_s[p0 + WW + 1]));
        out[(size_t)bc * 1024 + (rank * 16 + oy) * 32 + ox] = m;
    }
}

// ============================================================================
extern "C" void kernel_launch(void* const* d_in, const int* in_sizes, int n_in,
                              void* d_out, int out_size)
{
    const float* u   = (const float*)d_in[0];
    const float* rfs = (const float*)d_in[1];
    if (n_in >= 2 && in_sizes[0] == KK * HW && in_sizes[1] == BB * CC * HW) {
        const float* t = u; u = rfs; rfs = t;   // defensive: swapped order
    }
    float* out = (float*)d_out;

    rf_prep_kernel<<<KK + 32, 256>>>(rfs);
    rf_main_kernel<<<BB * CC * 2, 1024>>>(u, out);
}